// round 14
// baseline (speedup 1.0000x reference)
#include <cuda_runtime.h>
#include <cuda_fp16.h>

#define NTOKEN 150000
#define NEDGE  2400000
#define NSCANB ((NTOKEN + 255) / 256)   // 586 scan tiles
#define MVBLK  ((NTOKEN + 63) / 64)     // 2344 matvec tiles

// ---------------- scratch (static __device__, no allocation) ----------------
__device__ int    g_is64;
__device__ int    g_deg[NTOKEN];
__device__ int    g_off[NTOKEN];
__device__ float  g_dinv[NTOKEN];
__device__ int    g_rank[NEDGE];               // per-edge slot within its dst
__device__ int    g_srcs[NEDGE];               // CSR: src ids grouped by dst
__device__ __half g_Y2u[(size_t)NTOKEN * 64];  // 1024 * (emb[v] @ Wc)  (UNscaled by dinv)
__device__ __half g_g2h[(size_t)NTOKEN * 64];  // 1024 * dinv[v] * h2[v]
__device__ float2 g_Wc2[32 * 64];              // [k2][c] = (Wc[2k2][c], Wc[2k2+1][c])
__device__ float  g_bc[64];                    // b1 @ W2
__device__ int    g_bsum[NSCANB];

__device__ __forceinline__ void fma2(unsigned long long& d,
                                     unsigned long long a, unsigned long long b) {
    asm("fma.rn.f32x2 %0, %1, %2, %0;" : "+l"(d) : "l"(a), "l"(b));
}

// Fused prep: zero g_deg (blocks 0-146), Wc2/bc matmul (blocks 148-163),
// int64 detection (block 0 warp 0).
__global__ void prep_kernel(const void* __restrict__ edge,
                            const float* __restrict__ W1,
                            const float* __restrict__ b1,
                            const float* __restrict__ W2) {
    int b = blockIdx.x, t = threadIdx.x;
    if (b < 147) {
        int i = b * 256 + t;
        if (i < NTOKEN / 4) ((int4*)g_deg)[i] = make_int4(0, 0, 0, 0);
        if (b == 0 && t < 32) {
            const unsigned long long* e = (const unsigned long long*)edge;
            int bad = ((e[t] >> 32) != 0ull) || ((e[t + 32] >> 32) != 0ull);
            unsigned m = __ballot_sync(0xffffffffu, bad);
            if (t == 0) g_is64 = (m == 0u) ? 1 : 0;
        }
    } else if (b >= 148) {
        int idx = (b - 148) * 256 + t;          // 0..4095
        int i = idx >> 6, j = idx & 63;         // k row, c col
        float s = 0.0f;
#pragma unroll 8
        for (int k = 0; k < 128; k++) s += W1[i * 128 + k] * W2[k * 64 + j];
        ((float*)g_Wc2)[(((i >> 1) * 64 + j) << 1) + (i & 1)] = s;
        if (b == 148 && t < 64) {
            float bb = 0.0f;
#pragma unroll 8
            for (int k = 0; k < 128; k++) bb += b1[k] * W2[k * 64 + t];
            g_bc[t] = bb;
        }
    }
}

// Count + rank: 2 edges per thread via one wide load.
__global__ void count_rank_kernel(const void* __restrict__ edge) {
    long long p = (long long)blockIdx.x * blockDim.x + threadIdx.x;  // pair idx
    long long i = p * 2;
    if (i >= NEDGE) return;
    if (g_is64) {
        const int4* e = (const int4*)((const long long*)edge + NEDGE);
        int4 w = e[p];                        // dsts i, i+1 (low words x, z)
        g_rank[i]     = atomicAdd(&g_deg[w.x], 1);
        g_rank[i + 1] = atomicAdd(&g_deg[w.z], 1);
    } else {
        const int2* e = (const int2*)((const int*)edge + NEDGE);
        int2 w = e[p];
        g_rank[i]     = atomicAdd(&g_deg[w.x], 1);
        g_rank[i + 1] = atomicAdd(&g_deg[w.y], 1);
    }
}

// scan1: per-tile degree sums + dinv.
__global__ void scan1_kernel() {
    __shared__ int sh[256];
    int t = threadIdx.x;
    int i = blockIdx.x * 256 + t;
    int d = (i < NTOKEN) ? g_deg[i] : 0;
    if (i < NTOKEN) g_dinv[i] = rsqrtf((float)d + 1.0f);
    sh[t] = d;
    __syncthreads();
    for (int off = 128; off > 0; off >>= 1) {
        if (t < off) sh[t] += sh[t + off];
        __syncthreads();
    }
    if (t == 0) g_bsum[blockIdx.x] = sh[0];
}

// scan3: tile offset from g_bsum (L2-hot) + local exclusive scan -> g_off.
__global__ void scan3_kernel() {
    __shared__ int sh[256];
    __shared__ int sboff;
    int t = threadIdx.x;
    int partial = 0;
    for (int i = t; i < blockIdx.x; i += 256) partial += g_bsum[i];
    sh[t] = partial;
    __syncthreads();
    for (int off = 128; off > 0; off >>= 1) {
        if (t < off) sh[t] += sh[t + off];
        __syncthreads();
    }
    if (t == 0) sboff = sh[0];
    __syncthreads();
    int i = blockIdx.x * 256 + t;
    int d = (i < NTOKEN) ? g_deg[i] : 0;
    sh[t] = d;
    __syncthreads();
    for (int off = 1; off < 256; off <<= 1) {
        int u = (t >= off) ? sh[t - off] : 0;
        __syncthreads();
        sh[t] += u;
        __syncthreads();
    }
    if (i < NTOKEN) g_off[i] = sh[t] - d + sboff;
}

// Atomic-free scatter: pos = off[dst] + rank. 2 edges per thread, wide loads.
__global__ void scatter_kernel(const void* __restrict__ edge) {
    long long p = (long long)blockIdx.x * blockDim.x + threadIdx.x;
    long long i = p * 2;
    if (i >= NEDGE) return;
    int s0, s1, d0, d1;
    if (g_is64) {
        const int4* es = (const int4*)edge;
        const int4* ed = (const int4*)((const long long*)edge + NEDGE);
        int4 ws = es[p], wd = ed[p];
        s0 = ws.x; s1 = ws.z; d0 = wd.x; d1 = wd.z;
    } else {
        const int2* es = (const int2*)edge;
        const int2* ed = (const int2*)((const int*)edge + NEDGE);
        int2 ws = es[p], wd = ed[p];
        s0 = ws.x; s1 = ws.y; d0 = wd.x; d1 = wd.y;
    }
    int2 r = ((const int2*)g_rank)[p];
    g_srcs[g_off[d0] + r.x] = s0;
    g_srcs[g_off[d1] + r.y] = s1;
}

// Tiled GEMM, packed f32x2 FMA: Y2u[v] = fp16(1024 * (emb[v] @ Wc)).
// NO dinv dependency -> runs right after prep, overlapping the graph chain.
__global__ void matvec_kernel(const float* __restrict__ emb) {
    __shared__ float  s_emb[64 * 68];
    __shared__ float2 s_w2[32 * 64];
    int tid = threadIdx.x;
    int node0 = blockIdx.x * 64;

    for (int idx = tid; idx < 64 * 16; idx += 256) {
        int r = idx >> 4, c4 = idx & 15;
        int v = node0 + r;
        float4 val = (v < NTOKEN) ? ((const float4*)(emb + (size_t)v * 64))[c4]
                                  : make_float4(0.f, 0.f, 0.f, 0.f);
        *(float4*)&s_emb[r * 68 + c4 * 4] = val;
    }
    for (int idx = tid; idx < 1024; idx += 256)
        ((float4*)s_w2)[idx] = ((const float4*)g_Wc2)[idx];
    __syncthreads();

    int tc = tid & 15, tr = tid >> 4;
    int c0 = tc * 4;
    unsigned long long acc[4][4];
#pragma unroll
    for (int n = 0; n < 4; n++)
#pragma unroll
        for (int c = 0; c < 4; c++) acc[n][c] = 0ull;

    const float* erow0 = &s_emb[(tr * 4) * 68];
#pragma unroll 4
    for (int k4 = 0; k4 < 16; k4++) {
        ulonglong2 x[4];
#pragma unroll
        for (int n = 0; n < 4; n++)
            x[n] = *(const ulonglong2*)(erow0 + n * 68 + k4 * 4);
#pragma unroll
        for (int h = 0; h < 2; h++) {
            int k2 = k4 * 2 + h;
            ulonglong2 wA = *(const ulonglong2*)&s_w2[k2 * 64 + c0];
            ulonglong2 wB = *(const ulonglong2*)&s_w2[k2 * 64 + c0 + 2];
#pragma unroll
            for (int n = 0; n < 4; n++) {
                unsigned long long xp = h ? x[n].y : x[n].x;
                fma2(acc[n][0], xp, wA.x);
                fma2(acc[n][1], xp, wA.y);
                fma2(acc[n][2], xp, wB.x);
                fma2(acc[n][3], xp, wB.y);
            }
        }
    }

#pragma unroll
    for (int n = 0; n < 4; n++) {
        int v = node0 + tr * 4 + n;
        if (v < NTOKEN) {
            float r[4];
#pragma unroll
            for (int c = 0; c < 4; c++) {
                float2 f = *(float2*)&acc[n][c];
                r[c] = (f.x + f.y) * 1024.0f;
            }
            __half2 h0 = __floats2half2_rn(r[0], r[1]);
            __half2 h1 = __floats2half2_rn(r[2], r[3]);
            *(uint2*)&g_Y2u[(size_t)v * 64 + c0] =
                make_uint2(*(unsigned*)&h0, *(unsigned*)&h1);
        }
    }
}

// accS = dv*Y2u[v] + sum_s dinv[s]*Y2u[s]  (1024x-scaled fp32 accumulation)
// g2h[v] = dv*dv*accS + 1024*dv*bc
__global__ void agg_kernel() {
    int v = (blockIdx.x * blockDim.x + threadIdx.x) >> 5;
    int lane = threadIdx.x & 31;
    if (v >= NTOKEN) return;
    float dv = g_dinv[v];
    float2 y = __half22float2(((const __half2*)(g_Y2u + (size_t)v * 64))[lane]);
    float2 acc = make_float2(dv * y.x, dv * y.y);   // self term
    int o = g_off[v];
    int d = g_deg[v];
    int j = 0;
    for (; j + 3 < d; j += 4) {
        int s0 = g_srcs[o + j], s1 = g_srcs[o + j + 1];
        int s2 = g_srcs[o + j + 2], s3 = g_srcs[o + j + 3];
        float w0 = g_dinv[s0], w1 = g_dinv[s1], w2 = g_dinv[s2], w3 = g_dinv[s3];
        float2 y0 = __half22float2(((const __half2*)(g_Y2u + (size_t)s0 * 64))[lane]);
        float2 y1 = __half22float2(((const __half2*)(g_Y2u + (size_t)s1 * 64))[lane]);
        float2 y2 = __half22float2(((const __half2*)(g_Y2u + (size_t)s2 * 64))[lane]);
        float2 y3 = __half22float2(((const __half2*)(g_Y2u + (size_t)s3 * 64))[lane]);
        acc.x += w0 * y0.x + w1 * y1.x + w2 * y2.x + w3 * y3.x;
        acc.y += w0 * y0.y + w1 * y1.y + w2 * y2.y + w3 * y3.y;
    }
    for (; j < d; j++) {
        int s = g_srcs[o + j];
        float ws = g_dinv[s];
        float2 ys = __half22float2(((const __half2*)(g_Y2u + (size_t)s * 64))[lane]);
        acc.x += ws * ys.x; acc.y += ws * ys.y;
    }
    float2 bc = ((const float2*)g_bc)[lane];
    float k1 = dv * dv;
    float k2 = 1024.0f * dv;
    ((__half2*)(g_g2h + (size_t)v * 64))[lane] =
        __floats2half2_rn(k1 * acc.x + k2 * bc.x, k1 * acc.y + k2 * bc.y);
}

// out[pos] = dv*accG/1024 + b2,  accG = g2h[v] + sum g2h[s]
__global__ void out_kernel(const void* __restrict__ input, const float* __restrict__ b2,
                           float* __restrict__ out, int npos) {
    int st = g_is64 ? 2 : 1;
    const int* inp = (const int*)input;
    int w = (blockIdx.x * blockDim.x + threadIdx.x) >> 5;
    int lane = threadIdx.x & 31;
    if (w >= npos) return;
    int v = inp[(long long)w * st];
    float dv = g_dinv[v];
    float2 acc = __half22float2(((const __half2*)(g_g2h + (size_t)v * 64))[lane]);
    int o = g_off[v];
    int d = g_deg[v];
    int j = 0;
    for (; j + 3 < d; j += 4) {
        int s0 = g_srcs[o + j], s1 = g_srcs[o + j + 1];
        int s2 = g_srcs[o + j + 2], s3 = g_srcs[o + j + 3];
        float2 y0 = __half22float2(((const __half2*)(g_g2h + (size_t)s0 * 64))[lane]);
        float2 y1 = __half22float2(((const __half2*)(g_g2h + (size_t)s1 * 64))[lane]);
        float2 y2 = __half22float2(((const __half2*)(g_g2h + (size_t)s2 * 64))[lane]);
        float2 y3 = __half22float2(((const __half2*)(g_g2h + (size_t)s3 * 64))[lane]);
        acc.x += y0.x + y1.x + y2.x + y3.x;
        acc.y += y0.y + y1.y + y2.y + y3.y;
    }
    for (; j < d; j++) {
        int s = g_srcs[o + j];
        float2 ys = __half22float2(((const __half2*)(g_g2h + (size_t)s * 64))[lane]);
        acc.x += ys.x; acc.y += ys.y;
    }
    float2 b = ((const float2*)b2)[lane];
    float inv = dv * (1.0f / 1024.0f);
    float2 r;
    r.x = inv * acc.x + b.x;
    r.y = inv * acc.y + b.y;
    ((float2*)(out + (size_t)w * 64))[lane] = r;
}

extern "C" void kernel_launch(void* const* d_in, const int* in_sizes, int n_in,
                              void* d_out, int out_size) {
    const float* emb = (const float*)d_in[0];
    const float* W1  = (const float*)d_in[1];
    const float* b1  = (const float*)d_in[2];
    const float* W2  = (const float*)d_in[3];
    const float* b2  = (const float*)d_in[4];
    const void*  input = d_in[5];
    const void*  edge  = d_in[7];
    float* out = (float*)d_out;
    int npos = in_sizes[5];  // B*L = 12800

    static cudaStream_t s1 = nullptr;
    static cudaEvent_t evP = nullptr, ev2 = nullptr;
    if (!s1) {
        cudaStreamCreateWithFlags(&s1, cudaStreamNonBlocking);
        cudaEventCreateWithFlags(&evP, cudaEventDisableTiming);
        cudaEventCreateWithFlags(&ev2, cudaEventDisableTiming);
    }

    // main chain head: prep (zero + detect + Wc)
    prep_kernel<<<164, 256>>>(edge, W1, b1, W2);
    cudaEventRecord(evP, 0);

    // side: matvec depends only on prep (Wc) — overlaps the entire graph chain
    cudaStreamWaitEvent(s1, evP, 0);
    matvec_kernel<<<MVBLK, 256, 0, s1>>>(emb);
    cudaEventRecord(ev2, s1);

    // main graph chain
    count_rank_kernel<<<(NEDGE / 2 + 255) / 256, 256>>>(edge);
    scan1_kernel<<<NSCANB, 256>>>();
    scan3_kernel<<<NSCANB, 256>>>();
    scatter_kernel<<<(NEDGE / 2 + 255) / 256, 256>>>(edge);

    // join, then aggregate + output
    cudaStreamWaitEvent(0, ev2, 0);
    agg_kernel<<<(NTOKEN * 32 + 255) / 256, 256>>>();
    out_kernel<<<(npos * 32 + 255) / 256, 256>>>(input, b2, out, npos);
}

// round 15
// speedup vs baseline: 1.1752x; 1.1752x over previous
#include <cuda_runtime.h>
#include <cuda_fp16.h>
#include <mma.h>
using namespace nvcuda;

#define NTOKEN 150000
#define NEDGE  2400000
#define NSCANB ((NTOKEN + 255) / 256)   // 586 scan tiles
#define MVBLK  ((NTOKEN + 63) / 64)     // 2344 matvec tiles

// ---------------- scratch (static __device__, no allocation) ----------------
__device__ int    g_is64;
__device__ int    g_deg[NTOKEN];
__device__ int    g_off[NTOKEN];
__device__ float  g_dinv[NTOKEN];
__device__ int    g_rank[NEDGE];               // per-edge slot within its dst
__device__ int    g_srcs[NEDGE];               // CSR: src ids grouped by dst
__device__ __half g_Y2h[(size_t)NTOKEN * 64];  // 32  * dinv[v] * (emb[v] @ Wc)
__device__ __half g_g2h[(size_t)NTOKEN * 64];  // 1024* dinv[v] * h2[v]
__device__ float  g_Wc[64 * 64];               // W1 @ W2  (row k, col c)
__device__ float  g_bc[64];                    // b1 @ W2
__device__ int    g_bsum[NSCANB];

// Fused prep: zero g_deg (blocks 0-146), Wc/bc matmul (blocks 148-163),
// int64 detection (block 0 warp 0).
__global__ void prep_kernel(const void* __restrict__ edge,
                            const float* __restrict__ W1,
                            const float* __restrict__ b1,
                            const float* __restrict__ W2) {
    int b = blockIdx.x, t = threadIdx.x;
    if (b < 147) {
        int i = b * 256 + t;
        if (i < NTOKEN / 4) ((int4*)g_deg)[i] = make_int4(0, 0, 0, 0);
        if (b == 0 && t < 32) {
            const unsigned long long* e = (const unsigned long long*)edge;
            int bad = ((e[t] >> 32) != 0ull) || ((e[t + 32] >> 32) != 0ull);
            unsigned m = __ballot_sync(0xffffffffu, bad);
            if (t == 0) g_is64 = (m == 0u) ? 1 : 0;
        }
    } else if (b >= 148) {
        int idx = (b - 148) * 256 + t;          // 0..4095
        int i = idx >> 6, j = idx & 63;         // k row, c col
        float s = 0.0f;
#pragma unroll 8
        for (int k = 0; k < 128; k++) s += W1[i * 128 + k] * W2[k * 64 + j];
        g_Wc[i * 64 + j] = s;
        if (b == 148 && t < 64) {
            float bb = 0.0f;
#pragma unroll 8
            for (int k = 0; k < 128; k++) bb += b1[k] * W2[k * 64 + t];
            g_bc[t] = bb;
        }
    }
}

// Count + rank: 2 edges per thread via one wide load.
__global__ void count_rank_kernel(const void* __restrict__ edge) {
    long long p = (long long)blockIdx.x * blockDim.x + threadIdx.x;  // pair idx
    long long i = p * 2;
    if (i >= NEDGE) return;
    if (g_is64) {
        const int4* e = (const int4*)((const long long*)edge + NEDGE);
        int4 w = e[p];                        // dsts i, i+1 (low words x, z)
        g_rank[i]     = atomicAdd(&g_deg[w.x], 1);
        g_rank[i + 1] = atomicAdd(&g_deg[w.z], 1);
    } else {
        const int2* e = (const int2*)((const int*)edge + NEDGE);
        int2 w = e[p];
        g_rank[i]     = atomicAdd(&g_deg[w.x], 1);
        g_rank[i + 1] = atomicAdd(&g_deg[w.y], 1);
    }
}

// scan1: per-tile degree sums + dinv.
__global__ void scan1_kernel() {
    __shared__ int sh[256];
    int t = threadIdx.x;
    int i = blockIdx.x * 256 + t;
    int d = (i < NTOKEN) ? g_deg[i] : 0;
    if (i < NTOKEN) g_dinv[i] = rsqrtf((float)d + 1.0f);
    sh[t] = d;
    __syncthreads();
    for (int off = 128; off > 0; off >>= 1) {
        if (t < off) sh[t] += sh[t + off];
        __syncthreads();
    }
    if (t == 0) g_bsum[blockIdx.x] = sh[0];
}

// scan3: tile offset from g_bsum (L2-hot) + local exclusive scan -> g_off.
__global__ void scan3_kernel() {
    __shared__ int sh[256];
    __shared__ int sboff;
    int t = threadIdx.x;
    int partial = 0;
    for (int i = t; i < blockIdx.x; i += 256) partial += g_bsum[i];
    sh[t] = partial;
    __syncthreads();
    for (int off = 128; off > 0; off >>= 1) {
        if (t < off) sh[t] += sh[t + off];
        __syncthreads();
    }
    if (t == 0) sboff = sh[0];
    __syncthreads();
    int i = blockIdx.x * 256 + t;
    int d = (i < NTOKEN) ? g_deg[i] : 0;
    sh[t] = d;
    __syncthreads();
    for (int off = 1; off < 256; off <<= 1) {
        int u = (t >= off) ? sh[t - off] : 0;
        __syncthreads();
        sh[t] += u;
        __syncthreads();
    }
    if (i < NTOKEN) g_off[i] = sh[t] - d + sboff;
}

// Atomic-free scatter: pos = off[dst] + rank. 2 edges per thread, wide loads.
__global__ void scatter_kernel(const void* __restrict__ edge) {
    long long p = (long long)blockIdx.x * blockDim.x + threadIdx.x;
    long long i = p * 2;
    if (i >= NEDGE) return;
    int s0, s1, d0, d1;
    if (g_is64) {
        const int4* es = (const int4*)edge;
        const int4* ed = (const int4*)((const long long*)edge + NEDGE);
        int4 ws = es[p], wd = ed[p];
        s0 = ws.x; s1 = ws.z; d0 = wd.x; d1 = wd.z;
    } else {
        const int2* es = (const int2*)edge;
        const int2* ed = (const int2*)((const int*)edge + NEDGE);
        int2 ws = es[p], wd = ed[p];
        s0 = ws.x; s1 = ws.y; d0 = wd.x; d1 = wd.y;
    }
    int2 r = ((const int2*)g_rank)[p];
    g_srcs[g_off[d0] + r.x] = s0;
    g_srcs[g_off[d1] + r.y] = s1;
}

// Tensor-core matvec: Y2h[v] = fp16( dinv[v] * (emb_h[v] @ (32*Wc)_h) ).
// Block = 64 nodes x 64 cols; 8 warps, each computes two 16x16 wmma tiles.
__global__ void matvec_kernel(const float* __restrict__ emb) {
    __shared__ __half sA[64 * 72];     // emb tile, row-major, lda=72
    __shared__ __half sB[64 * 72];     // 32*Wc, row-major (k x c), ldb=72
    __shared__ float  sC[64 * 64];     // fp32 result tile
    __shared__ float  sD[64];          // dinv for rows
    int tid = threadIdx.x;
    int node0 = blockIdx.x * 64;

    // stage A: emb fp32 -> half (2048 half2 elems)
    for (int idx = tid; idx < 2048; idx += 256) {
        int r = idx >> 5, c2 = idx & 31;
        int v = node0 + r;
        float2 f = (v < NTOKEN) ? ((const float2*)(emb + (size_t)v * 64))[c2]
                                : make_float2(0.f, 0.f);
        *(__half2*)&sA[r * 72 + c2 * 2] = __floats2half2_rn(f.x, f.y);
    }
    // stage B: 32*Wc fp32 -> half
    for (int idx = tid; idx < 2048; idx += 256) {
        int k = idx >> 5, c2 = idx & 31;
        float2 f = ((const float2*)g_Wc)[k * 32 + c2];
        *(__half2*)&sB[k * 72 + c2 * 2] = __floats2half2_rn(32.0f * f.x, 32.0f * f.y);
    }
    if (tid < 64) {
        int v = node0 + tid;
        sD[tid] = (v < NTOKEN) ? g_dinv[v] : 0.0f;
    }
    __syncthreads();

    // 16 tiles of 16x16; warp w does tiles w and w+8
    int warp = tid >> 5;
#pragma unroll
    for (int rep = 0; rep < 2; rep++) {
        int tile = warp + rep * 8;
        int tr = (tile >> 2) * 16, tc = (tile & 3) * 16;
        wmma::fragment<wmma::accumulator, 16, 16, 16, float> fC;
        wmma::fill_fragment(fC, 0.0f);
#pragma unroll
        for (int kk = 0; kk < 4; kk++) {
            wmma::fragment<wmma::matrix_a, 16, 16, 16, __half, wmma::row_major> fA;
            wmma::fragment<wmma::matrix_b, 16, 16, 16, __half, wmma::row_major> fB;
            wmma::load_matrix_sync(fA, &sA[tr * 72 + kk * 16], 72);
            wmma::load_matrix_sync(fB, &sB[(kk * 16) * 72 + tc], 72);
            wmma::mma_sync(fC, fA, fB, fC);
        }
        wmma::store_matrix_sync(&sC[tr * 64 + tc], fC, 64, wmma::mem_row_major);
    }
    __syncthreads();

    // writeout: Y2h = half(dinv * C), 2048 half2
    for (int idx = tid; idx < 2048; idx += 256) {
        int r = idx >> 5, c2 = idx & 31;
        int v = node0 + r;
        if (v < NTOKEN) {
            float dv = sD[r];
            float2 f = ((const float2*)sC)[r * 32 + c2];
            ((__half2*)(g_Y2h + (size_t)v * 64))[c2] =
                __floats2half2_rn(dv * f.x, dv * f.y);
        }
    }
}

// g2h[v] = 32*dv*dv*accS + 1024*dv*bc   (accS = 32x-scaled fp32 accumulation)
__global__ void agg_kernel() {
    int v = (blockIdx.x * blockDim.x + threadIdx.x) >> 5;
    int lane = threadIdx.x & 31;
    if (v >= NTOKEN) return;
    float dv = g_dinv[v];
    float2 acc = __half22float2(((const __half2*)(g_Y2h + (size_t)v * 64))[lane]);
    int o = g_off[v];
    int d = g_deg[v];
    int j = 0;
    for (; j + 3 < d; j += 4) {
        int s0 = g_srcs[o + j], s1 = g_srcs[o + j + 1];
        int s2 = g_srcs[o + j + 2], s3 = g_srcs[o + j + 3];
        float2 y0 = __half22float2(((const __half2*)(g_Y2h + (size_t)s0 * 64))[lane]);
        float2 y1 = __half22float2(((const __half2*)(g_Y2h + (size_t)s1 * 64))[lane]);
        float2 y2 = __half22float2(((const __half2*)(g_Y2h + (size_t)s2 * 64))[lane]);
        float2 y3 = __half22float2(((const __half2*)(g_Y2h + (size_t)s3 * 64))[lane]);
        acc.x += y0.x + y1.x + y2.x + y3.x;
        acc.y += y0.y + y1.y + y2.y + y3.y;
    }
    for (; j < d; j++) {
        int s = g_srcs[o + j];
        float2 y = __half22float2(((const __half2*)(g_Y2h + (size_t)s * 64))[lane]);
        acc.x += y.x; acc.y += y.y;
    }
    float2 bc = ((const float2*)g_bc)[lane];
    float k1 = 32.0f * dv * dv;
    float k2 = 1024.0f * dv;
    ((__half2*)(g_g2h + (size_t)v * 64))[lane] =
        __floats2half2_rn(k1 * acc.x + k2 * bc.x, k1 * acc.y + k2 * bc.y);
}

// out[pos] = dv*accG/1024 + b2
__global__ void out_kernel(const void* __restrict__ input, const float* __restrict__ b2,
                           float* __restrict__ out, int npos) {
    int st = g_is64 ? 2 : 1;
    const int* inp = (const int*)input;
    int w = (blockIdx.x * blockDim.x + threadIdx.x) >> 5;
    int lane = threadIdx.x & 31;
    if (w >= npos) return;
    int v = inp[(long long)w * st];
    float dv = g_dinv[v];
    float2 acc = __half22float2(((const __half2*)(g_g2h + (size_t)v * 64))[lane]);
    int o = g_off[v];
    int d = g_deg[v];
    int j = 0;
    for (; j + 3 < d; j += 4) {
        int s0 = g_srcs[o + j], s1 = g_srcs[o + j + 1];
        int s2 = g_srcs[o + j + 2], s3 = g_srcs[o + j + 3];
        float2 y0 = __half22float2(((const __half2*)(g_g2h + (size_t)s0 * 64))[lane]);
        float2 y1 = __half22float2(((const __half2*)(g_g2h + (size_t)s1 * 64))[lane]);
        float2 y2 = __half22float2(((const __half2*)(g_g2h + (size_t)s2 * 64))[lane]);
        float2 y3 = __half22float2(((const __half2*)(g_g2h + (size_t)s3 * 64))[lane]);
        acc.x += y0.x + y1.x + y2.x + y3.x;
        acc.y += y0.y + y1.y + y2.y + y3.y;
    }
    for (; j < d; j++) {
        int s = g_srcs[o + j];
        float2 ys = __half22float2(((const __half2*)(g_g2h + (size_t)s * 64))[lane]);
        acc.x += ys.x; acc.y += ys.y;
    }
    float2 b = ((const float2*)b2)[lane];
    float inv = dv * (1.0f / 1024.0f);
    float2 r;
    r.x = inv * acc.x + b.x;
    r.y = inv * acc.y + b.y;
    ((float2*)(out + (size_t)w * 64))[lane] = r;
}

extern "C" void kernel_launch(void* const* d_in, const int* in_sizes, int n_in,
                              void* d_out, int out_size) {
    const float* emb = (const float*)d_in[0];
    const float* W1  = (const float*)d_in[1];
    const float* b1  = (const float*)d_in[2];
    const float* W2  = (const float*)d_in[3];
    const float* b2  = (const float*)d_in[4];
    const void*  input = d_in[5];
    const void*  edge  = d_in[7];
    float* out = (float*)d_out;
    int npos = in_sizes[5];  // B*L = 12800

    // Pure serial, single stream: 8 graph nodes, zero event nodes.
    prep_kernel<<<164, 256>>>(edge, W1, b1, W2);
    count_rank_kernel<<<(NEDGE / 2 + 255) / 256, 256>>>(edge);
    scan1_kernel<<<NSCANB, 256>>>();
    scan3_kernel<<<NSCANB, 256>>>();
    scatter_kernel<<<(NEDGE / 2 + 255) / 256, 256>>>(edge);
    matvec_kernel<<<MVBLK, 256>>>(emb);
    agg_kernel<<<(NTOKEN * 32 + 255) / 256, 256>>>();
    out_kernel<<<(npos * 32 + 255) / 256, 256>>>(input, b2, out, npos);
}